// round 2
// baseline (speedup 1.0000x reference)
#include <cuda_runtime.h>
#include <cuda_bf16.h>

// Problem: B=32 images of 512x512 fp32 (output, density_map), 3 int64 bboxes
// per batch, scalar num_objects. Produce 3 fp32 losses.
//
// Single streaming pass computes everything (box sums done via masked
// accumulation instead of an integral image). Deterministic: per-block double
// partials + fixed-order tree reduction, no atomics.

#define IMG_H 512
#define IMG_W 512
#define HW (IMG_H * IMG_W)        // 262144
#define NBATCH 32
#define NBOX 3
#define BLOCKS_PER_BATCH 128      // each block: 512 float4 = 2048 elems
#define NBLOCKS (NBATCH * BLOCKS_PER_BATCH)   // 4096
#define NPART 5                   // sq, bdiff, box0, box1, box2

// Per-block partials: [block][5] doubles. 4096*5*8 = 160 KB static scratch.
__device__ double g_part[NBLOCKS * NPART];

__global__ __launch_bounds__(256, 8)
void crit_main_kernel(const float* __restrict__ out_p,
                      const float* __restrict__ dmp_p,
                      const long long* __restrict__ bbox_p)
{
    const int b   = blockIdx.x >> 7;      // batch
    const int blk = blockIdx.x & 127;     // block within batch
    const int t   = threadIdx.x;

    // Load + clip this batch's 3 bboxes into shared
    __shared__ int sbb[NBOX * 4];
    if (t < NBOX * 4) {
        long long v = bbox_p[(size_t)b * NBOX * 4 + t];
        if (v < 0) v = 0;
        if (v > IMG_W) v = IMG_W;
        sbb[t] = (int)v;
    }
    __syncthreads();

    int bx1[NBOX], by1[NBOX], bx2[NBOX], by2[NBOX];
#pragma unroll
    for (int j = 0; j < NBOX; j++) {
        bx1[j] = sbb[j * 4 + 0];
        by1[j] = sbb[j * 4 + 1];
        bx2[j] = max(sbb[j * 4 + 2], bx1[j]);
        by2[j] = max(sbb[j * 4 + 3], by1[j]);
    }

    const float4* o4 = (const float4*)(out_p + (size_t)b * HW);
    const float4* d4 = (const float4*)(dmp_p + (size_t)b * HW);

    float sq = 0.f, bd = 0.f;
    float bs0 = 0.f, bs1 = 0.f, bs2 = 0.f;

#pragma unroll
    for (int it = 0; it < 2; it++) {
        int i = blk * 512 + it * 256 + t;      // float4 index in [0, 65536)
        float4 o = o4[i];
        float4 d = d4[i];
        float dx = o.x - d.x, dy = o.y - d.y, dz = o.z - d.z, dw = o.w - d.w;
        sq += dx * dx + dy * dy + dz * dz + dw * dw;
        bd += (dx + dy) + (dz + dw);

        int pix = i << 2;                      // element index in image
        int y   = pix >> 9;                    // row
        int x0  = pix & 511;                   // first of 4 columns

        float bsl[NBOX] = {0.f, 0.f, 0.f};
#pragma unroll
        for (int j = 0; j < NBOX; j++) {
            if (y >= by1[j] && y < by2[j]) {
                float s = 0.f;
                if (x0     >= bx1[j] && x0     < bx2[j]) s += o.x;
                if (x0 + 1 >= bx1[j] && x0 + 1 < bx2[j]) s += o.y;
                if (x0 + 2 >= bx1[j] && x0 + 2 < bx2[j]) s += o.z;
                if (x0 + 3 >= bx1[j] && x0 + 3 < bx2[j]) s += o.w;
                bsl[j] = s;
            }
        }
        bs0 += bsl[0]; bs1 += bsl[1]; bs2 += bsl[2];
    }

    // Block reduce 5 floats: warp shuffle then shared across 8 warps.
    float v[NPART] = {sq, bd, bs0, bs1, bs2};
#pragma unroll
    for (int k = 0; k < NPART; k++) {
#pragma unroll
        for (int off = 16; off > 0; off >>= 1)
            v[k] += __shfl_xor_sync(0xFFFFFFFFu, v[k], off);
    }
    __shared__ float wsum[8][NPART];
    int wid = t >> 5, lid = t & 31;
    if (lid == 0) {
#pragma unroll
        for (int k = 0; k < NPART; k++) wsum[wid][k] = v[k];
    }
    __syncthreads();
    if (wid == 0 && lid == 0) {
#pragma unroll
        for (int k = 0; k < NPART; k++) {
            float s = wsum[0][k];
#pragma unroll
            for (int w = 1; w < 8; w++) s += wsum[w][k];
            g_part[(size_t)blockIdx.x * NPART + k] = (double)s;
        }
    }
}

__global__ __launch_bounds__(256)
void crit_finalize_kernel(float* __restrict__ out3,
                          const unsigned char* __restrict__ nobj_ptr)
{
    __shared__ double sh[256];
    int t = threadIdx.x;

    // --- dmap squared-error total ---
    double s = 0.0;
    for (int i = t; i < NBLOCKS; i += 256)
        s += g_part[(size_t)i * NPART + 0];
    sh[t] = s;
    __syncthreads();
    for (int o = 128; o > 0; o >>= 1) {
        if (t < o) sh[t] += sh[t + o];
        __syncthreads();
    }
    double total_sq = sh[0];
    __syncthreads();

    // --- count loss: per-batch sum(o-d), squared, averaged ---
    double c = 0.0;
    if (t < NBATCH) {
        double bd = 0.0;
        for (int i = 0; i < BLOCKS_PER_BATCH; i++)
            bd += g_part[(size_t)(t * BLOCKS_PER_BATCH + i) * NPART + 1];
        c = bd * bd;
    }
    sh[t] = c;
    __syncthreads();
    for (int o = 128; o > 0; o >>= 1) {
        if (t < o) sh[t] += sh[t + o];
        __syncthreads();
    }
    double count_loss = sh[0] / (double)NBATCH;
    __syncthreads();

    // --- min-count loss: relu(1 - box_sum) summed over 96 boxes ---
    double m = 0.0;
    if (t < NBATCH * NBOX) {
        int b = t / NBOX, j = t % NBOX;
        double bx = 0.0;
        for (int i = 0; i < BLOCKS_PER_BATCH; i++)
            bx += g_part[(size_t)(b * BLOCKS_PER_BATCH + i) * NPART + 2 + j];
        double r = 1.0 - bx;
        m = (r > 0.0) ? r : 0.0;
    }
    sh[t] = m;
    __syncthreads();
    for (int o = 128; o > 0; o >>= 1) {
        if (t < o) sh[t] += sh[t + o];
        __syncthreads();
    }

    if (t == 0) {
        // Decode num_objects robustly (int32/int64 little-endian, or fp32).
        double num = 96.0;
        if (nobj_ptr) {
            int iv;
            memcpy(&iv, nobj_ptr, sizeof(int));
            if (iv > 0 && iv < (1 << 26)) {
                num = (double)iv;
            } else {
                float fv = __int_as_float(iv);
                if (fv > 0.5f && fv < 1e8f) num = (double)fv;
            }
        }
        out3[0] = (float)(total_sq / num);
        out3[1] = (float)count_loss;
        out3[2] = (float)sh[0];
    }
}

extern "C" void kernel_launch(void* const* d_in, const int* in_sizes, int n_in,
                              void* d_out, int out_size)
{
    const float*     out_p  = (const float*)d_in[0];
    const float*     dmp_p  = (const float*)d_in[1];
    const long long* bbox_p = (const long long*)d_in[2];
    const unsigned char* nobj = (n_in > 3) ? (const unsigned char*)d_in[3] : nullptr;
    float* o = (float*)d_out;
    (void)in_sizes; (void)out_size;

    crit_main_kernel<<<NBLOCKS, 256>>>(out_p, dmp_p, bbox_p);
    crit_finalize_kernel<<<1, 256>>>(o, nobj);
}

// round 3
// speedup vs baseline: 1.2854x; 1.2854x over previous
#include <cuda_runtime.h>
#include <cuda_bf16.h>

// B=32 images of 512x512 fp32 (output, density_map), 3 int64 bboxes/batch.
// Single kernel: streaming pass + last-block finalization (threadfence
// reduction). Deterministic: fixed-order reductions, counter atomics only.

#define IMG_H 512
#define IMG_W 512
#define HW (IMG_H * IMG_W)        // 262144
#define NBATCH 32
#define NBOX 3
#define BPB 32                    // blocks per batch
#define NB (NBATCH * BPB)         // 1024 blocks
#define ITERS 8                   // float4 iterations per thread (8192 elems/block)

__device__ float g_sq[NB];
__device__ float g_bd[NB];
__device__ float g_box[NBOX][NB];
__device__ unsigned int g_count;  // zero-init at load; reset by last block

__global__ __launch_bounds__(256, 8)
void crit_kernel(const float* __restrict__ out_p,
                 const float* __restrict__ dmp_p,
                 const long long* __restrict__ bbox_p,
                 float* __restrict__ out3,
                 const unsigned char* __restrict__ nobj_ptr)
{
    const int bid = blockIdx.x;
    const int b   = bid >> 5;     // batch
    const int blk = bid & 31;     // block within batch
    const int t   = threadIdx.x;
    const int wid = t >> 5, lid = t & 31;

    // Load + clip this batch's 3 bboxes into shared
    __shared__ int sbb[NBOX * 4];
    if (t < NBOX * 4) {
        long long v = bbox_p[(size_t)b * NBOX * 4 + t];
        if (v < 0) v = 0;
        if (v > IMG_W) v = IMG_W;
        sbb[t] = (int)v;
    }
    __syncthreads();

    int bx1[NBOX], by1[NBOX], bx2[NBOX], by2[NBOX];
#pragma unroll
    for (int j = 0; j < NBOX; j++) {
        bx1[j] = sbb[j * 4 + 0];
        by1[j] = sbb[j * 4 + 1];
        bx2[j] = max(sbb[j * 4 + 2], bx1[j]);
        by2[j] = max(sbb[j * 4 + 3], by1[j]);
    }

    const float4* o4 = (const float4*)(out_p + (size_t)b * HW);
    const float4* d4 = (const float4*)(dmp_p + (size_t)b * HW);

    float sq = 0.f, bd = 0.f;
    float bs[NBOX] = {0.f, 0.f, 0.f};

#pragma unroll
    for (int it = 0; it < ITERS; it++) {
        int i = blk * 2048 + it * 256 + t;     // float4 index in [0, 65536)
        float4 o = o4[i];
        float4 d = d4[i];
        float dx = o.x - d.x, dy = o.y - d.y, dz = o.z - d.z, dw = o.w - d.w;
        sq += dx * dx + dy * dy + dz * dz + dw * dw;
        bd += (dx + dy) + (dz + dw);

        int pix = i << 2;
        int y   = pix >> 9;
        int x0  = pix & 511;
#pragma unroll
        for (int j = 0; j < NBOX; j++) {
            if (y >= by1[j] && y < by2[j]) {
                float s = 0.f;
                if (x0     >= bx1[j] && x0     < bx2[j]) s += o.x;
                if (x0 + 1 >= bx1[j] && x0 + 1 < bx2[j]) s += o.y;
                if (x0 + 2 >= bx1[j] && x0 + 2 < bx2[j]) s += o.z;
                if (x0 + 3 >= bx1[j] && x0 + 3 < bx2[j]) s += o.w;
                bs[j] += s;
            }
        }
    }

    // Block reduce 5 floats: warp shuffle, then across 8 warps via shared.
    float v5[5] = {sq, bd, bs[0], bs[1], bs[2]};
#pragma unroll
    for (int k = 0; k < 5; k++) {
#pragma unroll
        for (int off = 16; off > 0; off >>= 1)
            v5[k] += __shfl_xor_sync(0xFFFFFFFFu, v5[k], off);
    }
    __shared__ float wsum[8][5];
    if (lid == 0) {
#pragma unroll
        for (int k = 0; k < 5; k++) wsum[wid][k] = v5[k];
    }
    __syncthreads();

    __shared__ bool isLast;
    if (t == 0) {
        float a0 = 0, a1 = 0, a2 = 0, a3 = 0, a4 = 0;
#pragma unroll
        for (int w = 0; w < 8; w++) {
            a0 += wsum[w][0]; a1 += wsum[w][1]; a2 += wsum[w][2];
            a3 += wsum[w][3]; a4 += wsum[w][4];
        }
        g_sq[bid]     = a0;
        g_bd[bid]     = a1;
        g_box[0][bid] = a2;
        g_box[1][bid] = a3;
        g_box[2][bid] = a4;
        __threadfence();
        unsigned int old = atomicAdd(&g_count, 1u);
        isLast = (old == NB - 1);
    }
    __syncthreads();
    if (!isLast) return;

    // ---------- last-block finalization (partials hot in L2) ----------
    __shared__ double shd[256];
    __shared__ double sh_bd2[NBATCH];
    __shared__ double sh_m[NBATCH * NBOX];

    // dmap squared-error total: 1024 floats, 4 coalesced loads/thread
    {
        double s = 0.0;
#pragma unroll
        for (int i = 0; i < 4; i++)
            s += (double)__ldcg(&g_sq[i * 256 + t]);
        shd[t] = s;
    }
    __syncthreads();
#pragma unroll
    for (int o = 128; o > 0; o >>= 1) {
        if (t < o) shd[t] += shd[t + o];
        __syncthreads();
    }
    double total_sq = shd[0];

    // count diff per batch: one warp per batch (8 warps x 4 batches)
#pragma unroll
    for (int bb = wid; bb < NBATCH; bb += 8) {
        double v = (double)__ldcg(&g_bd[bb * BPB + lid]);
#pragma unroll
        for (int off = 16; off > 0; off >>= 1)
            v += __shfl_xor_sync(0xFFFFFFFFu, v, off);
        if (lid == 0) sh_bd2[bb] = v * v;
    }

    // box sums: one warp per (batch, box) pair (8 warps x 12 pairs)
#pragma unroll
    for (int p = wid; p < NBATCH * NBOX; p += 8) {
        int bb = p / NBOX, k = p % NBOX;
        double v = (double)__ldcg(&g_box[k][bb * BPB + lid]);
#pragma unroll
        for (int off = 16; off > 0; off >>= 1)
            v += __shfl_xor_sync(0xFFFFFFFFu, v, off);
        if (lid == 0) {
            double r = 1.0 - v;
            sh_m[p] = (r > 0.0) ? r : 0.0;
        }
    }
    __syncthreads();

    if (wid == 0) {
        double c = sh_bd2[lid];
        double m = sh_m[lid] + sh_m[lid + 32] + sh_m[lid + 64];
#pragma unroll
        for (int off = 16; off > 0; off >>= 1) {
            c += __shfl_xor_sync(0xFFFFFFFFu, c, off);
            m += __shfl_xor_sync(0xFFFFFFFFu, m, off);
        }
        if (lid == 0) {
            // Decode num_objects robustly (int32/int64 LE, or fp32).
            double num = 96.0;
            if (nobj_ptr) {
                int iv;
                memcpy(&iv, nobj_ptr, sizeof(int));
                if (iv > 0 && iv < (1 << 26)) {
                    num = (double)iv;
                } else {
                    float fv = __int_as_float(iv);
                    if (fv > 0.5f && fv < 1e8f) num = (double)fv;
                }
            }
            out3[0] = (float)(total_sq / num);
            out3[1] = (float)(c / (double)NBATCH);
            out3[2] = (float)m;
            g_count = 0;   // reset for next graph replay
        }
    }
}

extern "C" void kernel_launch(void* const* d_in, const int* in_sizes, int n_in,
                              void* d_out, int out_size)
{
    const float*     out_p  = (const float*)d_in[0];
    const float*     dmp_p  = (const float*)d_in[1];
    const long long* bbox_p = (const long long*)d_in[2];
    const unsigned char* nobj = (n_in > 3) ? (const unsigned char*)d_in[3] : nullptr;
    (void)in_sizes; (void)out_size;

    crit_kernel<<<NB, 256>>>(out_p, dmp_p, bbox_p, (float*)d_out, nobj);
}

// round 5
// speedup vs baseline: 1.3903x; 1.0816x over previous
#include <cuda_runtime.h>
#include <cuda_bf16.h>

// B=32 images of 512x512 fp32 (output, density_map), 3 int64 bboxes/batch.
// Single kernel: streaming pass + last-block finalization (threadfence
// reduction). Deterministic: fixed-order reductions, counter atomics only.
//
// R4: launch_bounds(256,4) -> 64 regs; explicit 4-deep LDG.128 batching
// (MLP_p1 = 8) to break the latency bound seen in R3 (29% DRAM, issue 25%).

#define IMG_H 512
#define IMG_W 512
#define HW (IMG_H * IMG_W)        // 262144
#define NBATCH 32
#define NBOX 3
#define BPB 32                    // blocks per batch
#define NB (NBATCH * BPB)         // 1024 blocks
#define ITERS 8                   // float4 iterations per thread
#define GRP 4                     // load-batch depth

__device__ float g_sq[NB];
__device__ float g_bd[NB];
__device__ float g_box[NBOX][NB];
__device__ unsigned int g_count;  // zero-init at load; reset by last block

__global__ __launch_bounds__(256, 4)
void crit_kernel(const float* __restrict__ out_p,
                 const float* __restrict__ dmp_p,
                 const long long* __restrict__ bbox_p,
                 float* __restrict__ out3,
                 const unsigned char* __restrict__ nobj_ptr)
{
    const int bid = blockIdx.x;
    const int b   = bid >> 5;     // batch
    const int blk = bid & 31;     // block within batch
    const int t   = threadIdx.x;
    const int wid = t >> 5, lid = t & 31;

    // Load + clip this batch's 3 bboxes into shared
    __shared__ int sbb[NBOX * 4];
    if (t < NBOX * 4) {
        long long v = bbox_p[(size_t)b * NBOX * 4 + t];
        if (v < 0) v = 0;
        if (v > IMG_W) v = IMG_W;
        sbb[t] = (int)v;
    }
    __syncthreads();

    int bx1[NBOX], by1[NBOX], bx2[NBOX], by2[NBOX];
#pragma unroll
    for (int j = 0; j < NBOX; j++) {
        bx1[j] = sbb[j * 4 + 0];
        by1[j] = sbb[j * 4 + 1];
        bx2[j] = max(sbb[j * 4 + 2], bx1[j]);
        by2[j] = max(sbb[j * 4 + 3], by1[j]);
    }

    const float4* __restrict__ o4 = (const float4*)(out_p + (size_t)b * HW);
    const float4* __restrict__ d4 = (const float4*)(dmp_p + (size_t)b * HW);

    float sq = 0.f, bd = 0.f;
    float bs[NBOX] = {0.f, 0.f, 0.f};

    const int base = blk * 2048 + t;   // float4 index; +256 per iteration

#pragma unroll
    for (int g = 0; g < ITERS / GRP; g++) {
        float4 o_[GRP], d_[GRP];
        // Front-batch 2*GRP = 8 LDG.128 before any consumption.
#pragma unroll
        for (int u = 0; u < GRP; u++) {
            int i = base + (g * GRP + u) * 256;
            o_[u] = o4[i];
            d_[u] = d4[i];
        }
#pragma unroll
        for (int u = 0; u < GRP; u++) {
            float4 o = o_[u], d = d_[u];
            float dx = o.x - d.x, dy = o.y - d.y, dz = o.z - d.z, dw = o.w - d.w;
            sq += dx * dx + dy * dy + dz * dz + dw * dw;
            bd += (dx + dy) + (dz + dw);

            int i   = base + (g * GRP + u) * 256;
            int pix = i << 2;
            int y   = pix >> 9;
            int x0  = pix & 511;
#pragma unroll
            for (int j = 0; j < NBOX; j++) {
                if (y >= by1[j] && y < by2[j]) {
                    float s = 0.f;
                    if (x0     >= bx1[j] && x0     < bx2[j]) s += o.x;
                    if (x0 + 1 >= bx1[j] && x0 + 1 < bx2[j]) s += o.y;
                    if (x0 + 2 >= bx1[j] && x0 + 2 < bx2[j]) s += o.z;
                    if (x0 + 3 >= bx1[j] && x0 + 3 < bx2[j]) s += o.w;
                    bs[j] += s;
                }
            }
        }
    }

    // Block reduce 5 floats: warp shuffle, then across 8 warps via shared.
    float v5[5] = {sq, bd, bs[0], bs[1], bs[2]};
#pragma unroll
    for (int k = 0; k < 5; k++) {
#pragma unroll
        for (int off = 16; off > 0; off >>= 1)
            v5[k] += __shfl_xor_sync(0xFFFFFFFFu, v5[k], off);
    }
    __shared__ float wsum[8][5];
    if (lid == 0) {
#pragma unroll
        for (int k = 0; k < 5; k++) wsum[wid][k] = v5[k];
    }
    __syncthreads();

    __shared__ bool isLast;
    if (t == 0) {
        float a0 = 0, a1 = 0, a2 = 0, a3 = 0, a4 = 0;
#pragma unroll
        for (int w = 0; w < 8; w++) {
            a0 += wsum[w][0]; a1 += wsum[w][1]; a2 += wsum[w][2];
            a3 += wsum[w][3]; a4 += wsum[w][4];
        }
        g_sq[bid]     = a0;
        g_bd[bid]     = a1;
        g_box[0][bid] = a2;
        g_box[1][bid] = a3;
        g_box[2][bid] = a4;
        __threadfence();
        unsigned int old = atomicAdd(&g_count, 1u);
        isLast = (old == NB - 1);
    }
    __syncthreads();
    if (!isLast) return;

    // ---------- last-block finalization (partials hot in L2) ----------
    __shared__ double shd[256];
    __shared__ double sh_bd2[NBATCH];
    __shared__ double sh_m[NBATCH * NBOX];

    // dmap squared-error total: 1024 floats, 4 coalesced loads/thread
    {
        double s = 0.0;
#pragma unroll
        for (int i = 0; i < 4; i++)
            s += (double)__ldcg(&g_sq[i * 256 + t]);
        shd[t] = s;
    }
    __syncthreads();
#pragma unroll
    for (int o = 128; o > 0; o >>= 1) {
        if (t < o) shd[t] += shd[t + o];
        __syncthreads();
    }
    double total_sq = shd[0];

    // count diff per batch: one warp per batch (8 warps x 4 batches)
#pragma unroll
    for (int bb = wid; bb < NBATCH; bb += 8) {
        double v = (double)__ldcg(&g_bd[bb * BPB + lid]);
#pragma unroll
        for (int off = 16; off > 0; off >>= 1)
            v += __shfl_xor_sync(0xFFFFFFFFu, v, off);
        if (lid == 0) sh_bd2[bb] = v * v;
    }

    // box sums: one warp per (batch, box) pair (8 warps x 12 pairs)
#pragma unroll
    for (int p = wid; p < NBATCH * NBOX; p += 8) {
        int bb = p / NBOX, k = p % NBOX;
        double v = (double)__ldcg(&g_box[k][bb * BPB + lid]);
#pragma unroll
        for (int off = 16; off > 0; off >>= 1)
            v += __shfl_xor_sync(0xFFFFFFFFu, v, off);
        if (lid == 0) {
            double r = 1.0 - v;
            sh_m[p] = (r > 0.0) ? r : 0.0;
        }
    }
    __syncthreads();

    if (wid == 0) {
        double c = sh_bd2[lid];
        double m = sh_m[lid] + sh_m[lid + 32] + sh_m[lid + 64];
#pragma unroll
        for (int off = 16; off > 0; off >>= 1) {
            c += __shfl_xor_sync(0xFFFFFFFFu, c, off);
            m += __shfl_xor_sync(0xFFFFFFFFu, m, off);
        }
        if (lid == 0) {
            // Decode num_objects robustly (int32/int64 LE, or fp32).
            double num = 96.0;
            if (nobj_ptr) {
                int iv;
                memcpy(&iv, nobj_ptr, sizeof(int));
                if (iv > 0 && iv < (1 << 26)) {
                    num = (double)iv;
                } else {
                    float fv = __int_as_float(iv);
                    if (fv > 0.5f && fv < 1e8f) num = (double)fv;
                }
            }
            out3[0] = (float)(total_sq / num);
            out3[1] = (float)(c / (double)NBATCH);
            out3[2] = (float)m;
            g_count = 0;   // reset for next graph replay
        }
    }
}

extern "C" void kernel_launch(void* const* d_in, const int* in_sizes, int n_in,
                              void* d_out, int out_size)
{
    const float*     out_p  = (const float*)d_in[0];
    const float*     dmp_p  = (const float*)d_in[1];
    const long long* bbox_p = (const long long*)d_in[2];
    const unsigned char* nobj = (n_in > 3) ? (const unsigned char*)d_in[3] : nullptr;
    (void)in_sizes; (void)out_size;

    crit_kernel<<<NB, 256>>>(out_p, dmp_p, bbox_p, (float*)d_out, nobj);
}